// round 13
// baseline (speedup 1.0000x reference)
#include <cuda_runtime.h>

#define SSIM_C1 1e-4f
#define SSIM_C2 9e-4f

// tile geometry: 64 x 64 outputs per block
#define TW 64
#define TH 64
#define HR 74            // halo rows (TH + 10)
#define RS2 33           // hbuf row stride in u64 units (33 col-pairs)
#define PS2 (HR * RS2)   // plane-group stride in u64 units
#define HB_BYTES (2 * PS2 * 8)   // 2 groups x PS2 u64
#define NBLOCKS (16*16*16)

typedef unsigned long long u64;
typedef unsigned int u32;

__device__ __align__(16) float g_partial[NBLOCKS];
__device__ int g_count = 0;

// 11-tap gaussian (size=11, sigma=1.5), normalized; symmetric
__device__ __forceinline__ float gw(int i) {
    const float W[6] = {0.00102838f, 0.00759876f, 0.03600080f,
                        0.10936070f, 0.21300556f, 0.26601172f};
    return W[(i < 6) ? i : (10 - i)];
}
__device__ __forceinline__ float gwz(int d) {
    return (d >= 0 && d <= 10) ? gw(d) : 0.f;
}

__device__ __forceinline__ u64 pack2(float lo, float hi) {
    u64 r;
    asm("mov.b64 %0, {%1, %2};" : "=l"(r) : "f"(lo), "f"(hi));
    return r;
}
__device__ __forceinline__ u64 dup2(float w) {
    u64 r;
    asm("mov.b64 %0, {%1, %1};" : "=l"(r) : "f"(w));
    return r;
}
__device__ __forceinline__ u64 fma2(u64 a, u64 b, u64 c) {
    u64 d;
    asm("fma.rn.f32x2 %0, %1, %2, %3;" : "=l"(d) : "l"(a), "l"(b), "l"(c));
    return d;
}
__device__ __forceinline__ u64 mul2(u64 a, u64 b) {
    u64 d;
    asm("mul.rn.f32x2 %0, %1, %2;" : "=l"(d) : "l"(a), "l"(b));
    return d;
}
__device__ __forceinline__ void unpack2(u64 v, float& lo, float& hi) {
    asm("mov.b64 {%0, %1}, %2;" : "=f"(lo), "=f"(hi) : "l"(v));
}

// pack f32x2 (u64) -> f16x2 (u32), lanes preserved
__device__ __forceinline__ u32 f2h2(u64 v) {
    u32 d;
    asm("{\n\t"
        ".reg .f32 a, b;\n\t"
        "mov.b64 {a, b}, %1;\n\t"
        "cvt.rn.f16x2.f32 %0, b, a;\n\t"
        "}" : "=r"(d) : "l"(v));
    return d;
}
// unpack f16x2 (u32) -> f32x2 (u64), lanes preserved
__device__ __forceinline__ u64 h2f2(u32 h) {
    u64 r;
    asm("{\n\t"
        ".reg .b16 lo, hi;\n\t"
        ".reg .f32 a, b;\n\t"
        "mov.b32 {lo, hi}, %1;\n\t"
        "cvt.f32.f16 a, lo;\n\t"
        "cvt.f32.f16 b, hi;\n\t"
        "mov.b64 %0, {a, b};\n\t"
        "}" : "=l"(r) : "r"(h));
    return r;
}
__device__ __forceinline__ u64 cat32(u32 lo, u32 hi) {
    u64 r;
    asm("mov.b64 %0, {%1, %2};" : "=l"(r) : "r"(lo), "r"(hi));
    return r;
}
__device__ __forceinline__ void split64(u64 v, u32& lo, u32& hi) {
    asm("mov.b64 {%0, %1}, %2;" : "=r"(lo), "=r"(hi) : "l"(v));
}

// packed adjacent-weight pair for output cols (2c2, 2c2+1): (W[d], W[d-1])
__device__ __forceinline__ u64 wpair(int d) {
    return pack2(gwz(d), gwz(d - 1));
}

// scatter one input position i (0..17) into 4 packed col-pair accumulators
// planes: 0 = s = x+y, 1 = d = x-y, 2 = s^2, 3 = d^2
__device__ __forceinline__ void hacc2(int i, float xa, float yb, u64 acc2[4][4]) {
    float sv = xa + yb, dv = xa - yb;
    u64 s2 = dup2(sv), d2 = dup2(dv);
    u64 ss = mul2(s2, s2), dd = mul2(d2, d2);
    #pragma unroll
    for (int c2 = 0; c2 < 4; c2++) {
        int di = i - 2 * c2;
        if (di >= 0 && di <= 11) {
            u64 wp = wpair(di);
            acc2[0][c2] = fma2(s2, wp, acc2[0][c2]);
            acc2[1][c2] = fma2(d2, wp, acc2[1][c2]);
            acc2[2][c2] = fma2(ss, wp, acc2[2][c2]);
            acc2[3][c2] = fma2(dd, wp, acc2[3][c2]);
        }
    }
}

__global__ __launch_bounds__(256, 4) void ssim_main(
    const float* __restrict__ img1,
    const float* __restrict__ img2,
    float* __restrict__ out)
{
    extern __shared__ __align__(16) u64 hb[];   // 2 groups: [s|d] and [ss|dd] f16x2 pairs
    __shared__ float warpSums[8];
    __shared__ int s_isLast;

    const int tid = threadIdx.x;
    const int bx = blockIdx.x, by = blockIdx.y, bz = blockIdx.z;
    const int row0 = by * TH;
    const int col0 = bx * TW;

    // ========== pass 1: horizontal conv of s,d,ss,dd -> interleaved f16x2 hbuf ==========
    // item = halo row r (0..73) x col-group g (0..7, 8 output cols = 4 pairs) -> 592 items
    for (int t = tid; t < HR * 8; t += 256) {
        int r = t >> 3, g = t & 7;
        int gr = row0 - 5 + r;
        u64 acc2[4][4];
        #pragma unroll
        for (int q = 0; q < 4; q++)
            #pragma unroll
            for (int c2 = 0; c2 < 4; c2++) acc2[q][c2] = 0;

        if ((unsigned)gr < 1024u) {
            const float* p1 = img1 + (size_t)bz * 1048576u + (size_t)gr * 1024u;
            const float* p2 = img2 + (size_t)bz * 1048576u + (size_t)gr * 1024u;
            int gb = col0 + 8 * g - 8;   // window: positions i=0..17 at cols gb+3..gb+20
            bool fast = (gb >= 0) && (gb + 24 <= 1024);
            if (fast) {
                #pragma unroll
                for (int m = 0; m < 6; m++) {
                    float4 av = *(const float4*)(p1 + gb + 4 * m);
                    float4 bv = *(const float4*)(p2 + gb + 4 * m);
                    int i0 = 4 * m - 3;
                    if (i0 + 0 >= 0 && i0 + 0 <= 17) hacc2(i0 + 0, av.x, bv.x, acc2);
                    if (i0 + 1 >= 0 && i0 + 1 <= 17) hacc2(i0 + 1, av.y, bv.y, acc2);
                    if (i0 + 2 >= 0 && i0 + 2 <= 17) hacc2(i0 + 2, av.z, bv.z, acc2);
                    if (i0 + 3 >= 0 && i0 + 3 <= 17) hacc2(i0 + 3, av.w, bv.w, acc2);
                }
            } else {
                #pragma unroll
                for (int i = 0; i < 18; i++) {
                    int gc = gb + 3 + i;
                    bool ok = (unsigned)gc < 1024u;
                    float xa = ok ? p1[gc] : 0.f;
                    float yb = ok ? p2[gc] : 0.f;
                    hacc2(i, xa, yb, acc2);
                }
            }
        }
        int sb = r * RS2 + 4 * g;
        #pragma unroll
        for (int c2 = 0; c2 < 4; c2++) {
            hb[sb + c2]       = cat32(f2h2(acc2[0][c2]), f2h2(acc2[1][c2]));   // (s, d)
            hb[PS2 + sb + c2] = cat32(f2h2(acc2[2][c2]), f2h2(acc2[3][c2]));   // (ss, dd)
        }
    }
    __syncthreads();

    // ========== pass 2: vertical conv (LDS.64 -> 2x h2f2 -> f32x2 fma, R=4) + SSIM ==========
    // item = col-pair p (0..31) x 4-row chunk c (0..15) -> 512 items, 2 per thread
    const u64 half2c  = dup2(0.5f);
    const u64 mhalf2c = dup2(-0.5f);
    const u64 c1p = dup2(SSIM_C1);
    const u64 c2p = dup2(SSIM_C2);
    const u64 m1p = dup2(-1.f);

    float ssum = 0.f;
    for (int it = tid; it < 512; it += 256) {
        int p = it & 31, c = it >> 5;
        u64 A[4][4];
        #pragma unroll
        for (int q = 0; q < 4; q++)
            #pragma unroll
            for (int j = 0; j < 4; j++) A[q][j] = 0;

        const u64* hp = &hb[(4 * c) * RS2 + p];
        #pragma unroll
        for (int k = 0; k < 14; k++) {
            u64 vA = hp[k * RS2];          // (s, d) half2 pair
            u64 vB = hp[PS2 + k * RS2];    // (ss, dd) half2 pair
            u32 sh, dh, ssh, ddh;
            split64(vA, sh, dh);
            split64(vB, ssh, ddh);
            u64 vs_ = h2f2(sh), vd_ = h2f2(dh), vss = h2f2(ssh), vdd = h2f2(ddh);
            #pragma unroll
            for (int j = 0; j < 4; j++) {
                int wi = k - j;
                if (wi >= 0 && wi <= 10) {
                    u64 w = dup2(gw(wi));
                    A[0][j] = fma2(w, vs_, A[0][j]);
                    A[1][j] = fma2(w, vd_, A[1][j]);
                    A[2][j] = fma2(w, vss, A[2][j]);
                    A[3][j] = fma2(w, vdd, A[3][j]);
                }
            }
        }
        #pragma unroll
        for (int j = 0; j < 4; j++) {
            u64 ms = A[0][j], md = A[1][j], ess = A[2][j], edd = A[3][j];
            u64 ms2 = mul2(ms, ms);
            u64 md2 = mul2(md, md);
            u64 vs = fma2(ms2, m1p, ess);                       // ess - ms2
            u64 vd = fma2(md2, m1p, edd);                       // edd - md2
            u64 numA = fma2(ms2, half2c, fma2(md2, mhalf2c, c1p));
            u64 denA = fma2(ms2, half2c, fma2(md2, half2c,  c1p));
            u64 numB = fma2(vs,  half2c, fma2(vd,  mhalf2c, c2p));
            u64 denB = fma2(vs,  half2c, fma2(vd,  half2c,  c2p));
            u64 num = mul2(numA, numB);
            u64 den = mul2(denA, denB);
            float n0, n1, d0, d1;
            unpack2(num, n0, n1);
            unpack2(den, d0, d1);
            ssum += __fdividef(n0, d0);
            ssum += __fdividef(n1, d1);
        }
    }

    // ========== block reduction (deterministic) ==========
    #pragma unroll
    for (int o = 16; o > 0; o >>= 1)
        ssum += __shfl_down_sync(0xffffffffu, ssum, o);
    const int wid = tid >> 5, lane = tid & 31;
    if (lane == 0) warpSums[wid] = ssum;
    __syncthreads();
    if (tid == 0) {
        float tot = 0.f;
        #pragma unroll
        for (int i = 0; i < 8; i++) tot += warpSums[i];
        int bid = bx + 16 * (by + 16 * bz);
        g_partial[bid] = tot;
        __threadfence();
        int prev = atomicAdd(&g_count, 1);
        s_isLast = (prev == NBLOCKS - 1);
    }
    __syncthreads();

    // ========== last block folds the global mean ==========
    if (s_isLast) {
        __shared__ double dsum[8];
        const float4* p4 = (const float4*)g_partial;   // 1024 float4
        double s = 0.0;
        #pragma unroll
        for (int i = 0; i < 4; i++) {
            float4 v = p4[tid + i * 256];
            s += (double)v.x + (double)v.y + (double)v.z + (double)v.w;
        }
        #pragma unroll
        for (int o = 16; o > 0; o >>= 1)
            s += __shfl_down_sync(0xffffffffu, s, o);
        if (lane == 0) dsum[wid] = s;
        __syncthreads();
        if (tid == 0) {
            double t = 0.0;
            #pragma unroll
            for (int i = 0; i < 8; i++) t += dsum[i];
            out[0] = (float)(t / 16777216.0);
            g_count = 0;   // reset for next graph replay
        }
    }
}

extern "C" void kernel_launch(void* const* d_in, const int* in_sizes, int n_in,
                              void* d_out, int out_size)
{
    const float* img1 = (const float*)d_in[0];
    const float* img2 = (const float*)d_in[1];
    float* out = (float*)d_out;

    cudaFuncSetAttribute(ssim_main, cudaFuncAttributeMaxDynamicSharedMemorySize, HB_BYTES);

    dim3 grid(16, 16, 16);   // 1024/64 x-tiles, 1024/64 y-tiles, 16 batch
    ssim_main<<<grid, 256, HB_BYTES>>>(img1, img2, out);
}

// round 14
// speedup vs baseline: 1.0071x; 1.0071x over previous
#include <cuda_runtime.h>

#define SSIM_C1 1e-4f
#define SSIM_C2 9e-4f

// tile geometry: 64 x 64 outputs per block
#define TW 64
#define TH 64
#define HR 74              // halo rows (TH + 10)
#define RS128 40           // hbuf row stride in uint4 units (swizzled 5g+c2 <= 38)
#define HB_BYTES (HR * RS128 * 16)
#define NBLOCKS (16*16*16)

typedef unsigned long long u64;
typedef unsigned int u32;

__device__ __align__(16) float g_partial[NBLOCKS];
__device__ int g_count = 0;

// 11-tap gaussian (size=11, sigma=1.5), normalized; symmetric
__device__ __forceinline__ float gw(int i) {
    const float W[6] = {0.00102838f, 0.00759876f, 0.03600080f,
                        0.10936070f, 0.21300556f, 0.26601172f};
    return W[(i < 6) ? i : (10 - i)];
}
__device__ __forceinline__ float gwz(int d) {
    return (d >= 0 && d <= 10) ? gw(d) : 0.f;
}

__device__ __forceinline__ u64 pack2(float lo, float hi) {
    u64 r;
    asm("mov.b64 %0, {%1, %2};" : "=l"(r) : "f"(lo), "f"(hi));
    return r;
}
__device__ __forceinline__ u64 dup2(float w) {
    u64 r;
    asm("mov.b64 %0, {%1, %1};" : "=l"(r) : "f"(w));
    return r;
}
__device__ __forceinline__ u64 fma2(u64 a, u64 b, u64 c) {
    u64 d;
    asm("fma.rn.f32x2 %0, %1, %2, %3;" : "=l"(d) : "l"(a), "l"(b), "l"(c));
    return d;
}
__device__ __forceinline__ u64 mul2(u64 a, u64 b) {
    u64 d;
    asm("mul.rn.f32x2 %0, %1, %2;" : "=l"(d) : "l"(a), "l"(b));
    return d;
}
__device__ __forceinline__ void unpack2(u64 v, float& lo, float& hi) {
    asm("mov.b64 {%0, %1}, %2;" : "=f"(lo), "=f"(hi) : "l"(v));
}

// pack f32x2 (u64) -> f16x2 (u32), lanes preserved
__device__ __forceinline__ u32 f2h2(u64 v) {
    u32 d;
    asm("{\n\t"
        ".reg .f32 a, b;\n\t"
        "mov.b64 {a, b}, %1;\n\t"
        "cvt.rn.f16x2.f32 %0, b, a;\n\t"
        "}" : "=r"(d) : "l"(v));
    return d;
}
// unpack f16x2 (u32) -> f32x2 (u64), lanes preserved
__device__ __forceinline__ u64 h2f2(u32 h) {
    u64 r;
    asm("{\n\t"
        ".reg .b16 lo, hi;\n\t"
        ".reg .f32 a, b;\n\t"
        "mov.b32 {lo, hi}, %1;\n\t"
        "cvt.f32.f16 a, lo;\n\t"
        "cvt.f32.f16 b, hi;\n\t"
        "mov.b64 %0, {a, b};\n\t"
        "}" : "=l"(r) : "r"(h));
    return r;
}

// packed adjacent-weight pair for output cols (2c2, 2c2+1): (W[d], W[d-1])
__device__ __forceinline__ u64 wpair(int d) {
    return pack2(gwz(d), gwz(d - 1));
}

// scatter one input position i (0..17) into 4 packed col-pair accumulators
// planes: 0 = s = x+y, 1 = d = x-y, 2 = s^2, 3 = d^2
__device__ __forceinline__ void hacc2(int i, float xa, float yb, u64 acc2[4][4]) {
    float sv = xa + yb, dv = xa - yb;
    u64 s2 = dup2(sv), d2 = dup2(dv);
    u64 ss = mul2(s2, s2), dd = mul2(d2, d2);
    #pragma unroll
    for (int c2 = 0; c2 < 4; c2++) {
        int di = i - 2 * c2;
        if (di >= 0 && di <= 11) {
            u64 wp = wpair(di);
            acc2[0][c2] = fma2(s2, wp, acc2[0][c2]);
            acc2[1][c2] = fma2(d2, wp, acc2[1][c2]);
            acc2[2][c2] = fma2(ss, wp, acc2[2][c2]);
            acc2[3][c2] = fma2(dd, wp, acc2[3][c2]);
        }
    }
}

__global__ __launch_bounds__(256, 4) void ssim_main(
    const float* __restrict__ img1,
    const float* __restrict__ img2,
    float* __restrict__ out)
{
    extern __shared__ __align__(16) uint4 hb[];   // f16x4 (s,d,ss,dd) per col-pair
    __shared__ float warpSums[8];
    __shared__ int s_isLast;

    const int tid = threadIdx.x;
    const int bx = blockIdx.x, by = blockIdx.y, bz = blockIdx.z;
    const int row0 = by * TH;
    const int col0 = bx * TW;

    // ========== pass 1: horizontal conv of s,d,ss,dd -> interleaved f16x4 hbuf ==========
    // item = halo row r (0..73) x col-group g (0..7, 8 output cols = 4 pairs) -> 592 items
    for (int t = tid; t < HR * 8; t += 256) {
        int r = t >> 3, g = t & 7;
        int gr = row0 - 5 + r;
        u64 acc2[4][4];
        #pragma unroll
        for (int q = 0; q < 4; q++)
            #pragma unroll
            for (int c2 = 0; c2 < 4; c2++) acc2[q][c2] = 0;

        if ((unsigned)gr < 1024u) {
            const float* p1 = img1 + (size_t)bz * 1048576u + (size_t)gr * 1024u;
            const float* p2 = img2 + (size_t)bz * 1048576u + (size_t)gr * 1024u;
            int gb = col0 + 8 * g - 8;   // window: positions i=0..17 at cols gb+3..gb+20
            bool fast = (gb >= 0) && (gb + 24 <= 1024);
            if (fast) {
                #pragma unroll
                for (int m = 0; m < 6; m++) {
                    float4 av = *(const float4*)(p1 + gb + 4 * m);
                    float4 bv = *(const float4*)(p2 + gb + 4 * m);
                    int i0 = 4 * m - 3;
                    if (i0 + 0 >= 0 && i0 + 0 <= 17) hacc2(i0 + 0, av.x, bv.x, acc2);
                    if (i0 + 1 >= 0 && i0 + 1 <= 17) hacc2(i0 + 1, av.y, bv.y, acc2);
                    if (i0 + 2 >= 0 && i0 + 2 <= 17) hacc2(i0 + 2, av.z, bv.z, acc2);
                    if (i0 + 3 >= 0 && i0 + 3 <= 17) hacc2(i0 + 3, av.w, bv.w, acc2);
                }
            } else {
                #pragma unroll
                for (int i = 0; i < 18; i++) {
                    int gc = gb + 3 + i;
                    bool ok = (unsigned)gc < 1024u;
                    float xa = ok ? p1[gc] : 0.f;
                    float yb = ok ? p2[gc] : 0.f;
                    hacc2(i, xa, yb, acc2);
                }
            }
        }
        // swizzled store: pair index = 5g + c2 (5g mod 8 is a permutation of g -> no bank-group conflicts)
        int sidx = r * RS128 + 5 * g;
        #pragma unroll
        for (int c2 = 0; c2 < 4; c2++) {
            uint4 v;
            v.x = f2h2(acc2[0][c2]);
            v.y = f2h2(acc2[1][c2]);
            v.z = f2h2(acc2[2][c2]);
            v.w = f2h2(acc2[3][c2]);
            hb[sidx + c2] = v;
        }
    }
    __syncthreads();

    // ========== pass 2: vertical conv (LDS.128 -> 4x h2f2 -> f32x2 fma, R=4) + SSIM ==========
    // item = col-pair p (0..31) x 4-row chunk c (0..15) -> 512 items, 2 per thread
    const u64 half2c  = dup2(0.5f);
    const u64 mhalf2c = dup2(-0.5f);
    const u64 c1p = dup2(SSIM_C1);
    const u64 c2p = dup2(SSIM_C2);
    const u64 m1p = dup2(-1.f);

    float ssum = 0.f;
    for (int it = tid; it < 512; it += 256) {
        int p = it & 31, c = it >> 5;
        int pidx = 5 * (p >> 2) + (p & 3);   // swizzled pair index
        u64 A[4][4];
        #pragma unroll
        for (int q = 0; q < 4; q++)
            #pragma unroll
            for (int j = 0; j < 4; j++) A[q][j] = 0;

        const uint4* hp = &hb[(4 * c) * RS128 + pidx];
        #pragma unroll
        for (int k = 0; k < 14; k++) {
            uint4 v = hp[k * RS128];
            u64 vs_ = h2f2(v.x), vd_ = h2f2(v.y), vss = h2f2(v.z), vdd = h2f2(v.w);
            #pragma unroll
            for (int j = 0; j < 4; j++) {
                int wi = k - j;
                if (wi >= 0 && wi <= 10) {
                    u64 w = dup2(gw(wi));
                    A[0][j] = fma2(w, vs_, A[0][j]);
                    A[1][j] = fma2(w, vd_, A[1][j]);
                    A[2][j] = fma2(w, vss, A[2][j]);
                    A[3][j] = fma2(w, vdd, A[3][j]);
                }
            }
        }
        #pragma unroll
        for (int j = 0; j < 4; j++) {
            u64 ms = A[0][j], md = A[1][j], ess = A[2][j], edd = A[3][j];
            u64 ms2 = mul2(ms, ms);
            u64 md2 = mul2(md, md);
            u64 vs = fma2(ms2, m1p, ess);                       // ess - ms2
            u64 vd = fma2(md2, m1p, edd);                       // edd - md2
            u64 numA = fma2(ms2, half2c, fma2(md2, mhalf2c, c1p));
            u64 denA = fma2(ms2, half2c, fma2(md2, half2c,  c1p));
            u64 numB = fma2(vs,  half2c, fma2(vd,  mhalf2c, c2p));
            u64 denB = fma2(vs,  half2c, fma2(vd,  half2c,  c2p));
            u64 num = mul2(numA, numB);
            u64 den = mul2(denA, denB);
            float n0, n1, d0, d1;
            unpack2(num, n0, n1);
            unpack2(den, d0, d1);
            ssum += __fdividef(n0, d0);
            ssum += __fdividef(n1, d1);
        }
    }

    // ========== block reduction (deterministic) ==========
    #pragma unroll
    for (int o = 16; o > 0; o >>= 1)
        ssum += __shfl_down_sync(0xffffffffu, ssum, o);
    const int wid = tid >> 5, lane = tid & 31;
    if (lane == 0) warpSums[wid] = ssum;
    __syncthreads();
    if (tid == 0) {
        float tot = 0.f;
        #pragma unroll
        for (int i = 0; i < 8; i++) tot += warpSums[i];
        int bid = bx + 16 * (by + 16 * bz);
        g_partial[bid] = tot;
        __threadfence();
        int prev = atomicAdd(&g_count, 1);
        s_isLast = (prev == NBLOCKS - 1);
    }
    __syncthreads();

    // ========== last block folds the global mean ==========
    if (s_isLast) {
        __shared__ double dsum[8];
        const float4* p4 = (const float4*)g_partial;   // 1024 float4
        double s = 0.0;
        #pragma unroll
        for (int i = 0; i < 4; i++) {
            float4 v = p4[tid + i * 256];
            s += (double)v.x + (double)v.y + (double)v.z + (double)v.w;
        }
        #pragma unroll
        for (int o = 16; o > 0; o >>= 1)
            s += __shfl_down_sync(0xffffffffu, s, o);
        if (lane == 0) dsum[wid] = s;
        __syncthreads();
        if (tid == 0) {
            double t = 0.0;
            #pragma unroll
            for (int i = 0; i < 8; i++) t += dsum[i];
            out[0] = (float)(t / 16777216.0);
            g_count = 0;   // reset for next graph replay
        }
    }
}

extern "C" void kernel_launch(void* const* d_in, const int* in_sizes, int n_in,
                              void* d_out, int out_size)
{
    const float* img1 = (const float*)d_in[0];
    const float* img2 = (const float*)d_in[1];
    float* out = (float*)d_out;

    cudaFuncSetAttribute(ssim_main, cudaFuncAttributeMaxDynamicSharedMemorySize, HB_BYTES);

    dim3 grid(16, 16, 16);   // 1024/64 x-tiles, 1024/64 y-tiles, 16 batch
    ssim_main<<<grid, 256, HB_BYTES>>>(img1, img2, out);
}